// round 4
// baseline (speedup 1.0000x reference)
#include <cuda_runtime.h>
#include <cstdint>

#define S_LEN 16384
#define D_DIM 256
#define V_DIM 8
#define K_HEADS 24

typedef unsigned long long u64;

__device__ __forceinline__ u64 packf2(float lo, float hi) {
    u64 r; asm("mov.b64 %0, {%1, %2};" : "=l"(r) : "f"(lo), "f"(hi)); return r;
}
__device__ __forceinline__ void unpackf2(u64 p, float& lo, float& hi) {
    asm("mov.b64 {%0, %1}, %2;" : "=f"(lo), "=f"(hi) : "l"(p));
}
__device__ __forceinline__ void fmaf2(u64& d, u64 a, u64 b) {
    asm("fma.rn.f32x2 %0, %1, %2, %0;" : "+l"(d) : "l"(a), "l"(b));
}
__device__ __forceinline__ u64 addf2(u64 a, u64 b) {
    u64 r; asm("add.rn.f32x2 %0, %1, %2;" : "=l"(r) : "l"(a), "l"(b)); return r;
}
__device__ __forceinline__ u64 shfl_xor64(u64 v, int m) {
    float lo, hi; unpackf2(v, lo, hi);
    lo = __shfl_xor_sync(0xffffffffu, lo, m);
    hi = __shfl_xor_sync(0xffffffffu, hi, m);
    return packf2(lo, hi);
}

__global__ __launch_bounds__(256, 2)
void attr_decoder_kernel(const float* __restrict__ feats,      // [N, 256]
                         const int*   __restrict__ mask_idx,   // [24, 16384]
                         const float* __restrict__ Wh,         // [24, 256, 8]
                         const float* __restrict__ bias,       // [24, 8]
                         float*       __restrict__ out)        // [24, 16384, 8]
{
    const int k    = blockIdx.y;
    const int lane = threadIdx.x & 31;
    const int warp = threadIdx.x >> 5;
    const int s0   = blockIdx.x * 256 + warp * 32;   // 32 rows per warp

    const int b4 = (lane >> 4) & 1;
    const int b3 = (lane >> 3) & 1;
    const int b2 = (lane >> 2) & 1;
    const int perm = 2 * b4 + b3;
    const int vown = 4 * b4 + 2 * b3 + b2;

    // ---- Per-head weights in registers, pre-permuted -> select-free fold.
    // Slot s holds v-pair q = s ^ perm; intra-pair order swapped when b2=1.
    u64 wp[8][4];
    const float4* wk = (const float4*)(Wh + (size_t)k * (D_DIM * V_DIM));
    #pragma unroll
    for (int i = 0; i < 8; ++i) {
        int d = lane * 8 + i;
        float4 A = wk[d * 2 + 0];
        float4 B = wk[d * 2 + 1];
        float pv[4][2] = {{A.x, A.y}, {A.z, A.w}, {B.x, B.y}, {B.z, B.w}};
        #pragma unroll
        for (int s = 0; s < 4; ++s) {
            int q = s ^ perm;
            wp[i][s] = packf2(pv[q][b2], pv[q][1 - b2]);
        }
    }
    const float bias_v = bias[k * V_DIM + vown];

    // One gather index per lane covers the warp's 32 rows.
    const int idxv = mask_idx[(size_t)k * S_LEN + s0 + lane];

    // ---- Load a 2-row pair (rows r, r+1) into 4 float4 registers.
    auto loadpair = [&](int r, float4& x0, float4& x1, float4& y0, float4& y1) {
        int ia = __shfl_sync(0xffffffffu, idxv, r);
        int ib = __shfl_sync(0xffffffffu, idxv, r + 1);
        const float4* pa = (const float4*)(feats + (size_t)ia * D_DIM) + lane * 2;
        const float4* pb = (const float4*)(feats + (size_t)ib * D_DIM) + lane * 2;
        x0 = pa[0]; x1 = pa[1]; y0 = pb[0]; y1 = pb[1];
    };

    // ---- Compute + interleaved fold for a row pair (independent chains).
    auto compute2 = [&](const float4& x0, const float4& x1,
                        const float4& y0, const float4& y1,
                        float& resA, float& resB) {
        const float fA[8] = {x0.x, x0.y, x0.z, x0.w, x1.x, x1.y, x1.z, x1.w};
        const float fB[8] = {y0.x, y0.y, y0.z, y0.w, y1.x, y1.y, y1.z, y1.w};
        u64 aA[4] = {0ull, 0ull, 0ull, 0ull};
        u64 aB[4] = {0ull, 0ull, 0ull, 0ull};
        #pragma unroll
        for (int i = 0; i < 8; ++i) {
            u64 da = packf2(fA[i], fA[i]);
            u64 db = packf2(fB[i], fB[i]);
            #pragma unroll
            for (int s = 0; s < 4; ++s) {
                fmaf2(aA[s], da, wp[i][s]);
                fmaf2(aB[s], db, wp[i][s]);
            }
        }
        // off16 fold: 4 pairs -> 2 (A and B interleaved for latency overlap)
        u64 sA2 = shfl_xor64(aA[2], 16);
        u64 sB2 = shfl_xor64(aB[2], 16);
        u64 sA3 = shfl_xor64(aA[3], 16);
        u64 sB3 = shfl_xor64(aB[3], 16);
        u64 tA0 = addf2(aA[0], sA2), tB0 = addf2(aB[0], sB2);
        u64 tA1 = addf2(aA[1], sA3), tB1 = addf2(aB[1], sB3);
        // off8 fold: 2 pairs -> 1
        u64 hA = shfl_xor64(tA1, 8);
        u64 hB = shfl_xor64(tB1, 8);
        u64 uA = addf2(tA0, hA);
        u64 uB = addf2(tB0, hB);
        // off4: intra-pair (pre-swapped by b2)
        float loA, hiA, loB, hiB;
        unpackf2(uA, loA, hiA);
        unpackf2(uB, loB, hiB);
        float wA = loA + __shfl_xor_sync(0xffffffffu, hiA, 4);
        float wB = loB + __shfl_xor_sync(0xffffffffu, hiB, 4);
        wA += __shfl_xor_sync(0xffffffffu, wA, 2);
        wB += __shfl_xor_sync(0xffffffffu, wB, 2);
        wA += __shfl_xor_sync(0xffffffffu, wA, 1);
        wB += __shfl_xor_sync(0xffffffffu, wB, 1);
        resA = wA + bias_v;
        resB = wB + bias_v;
    };

    float4 A0, A1, B0, B1;   // buffer 0 (pair p)
    float4 C0, C1, D0, D1;   // buffer 1 (pair p+1)
    loadpair(0, A0, A1, B0, B1);

    float keep = 0.0f;
    const int lm = lane & 3;

    #pragma unroll 2
    for (int p = 0; p < 16; p += 2) {
        // prefetch pair p+1 into buffer 1
        loadpair(2 * (p + 1), C0, C1, D0, D1);

        float rA, rB;
        compute2(A0, A1, B0, B1, rA, rB);        // rows 2p, 2p+1  (≡ 0,1 mod 4)
        if (lm == 0) keep = rA;
        else if (lm == 1) keep = rB;

        // prefetch pair p+2 into buffer 0
        if (p + 2 < 16) loadpair(2 * (p + 2), A0, A1, B0, B1);

        compute2(C0, C1, D0, D1, rA, rB);        // rows 2p+2, 2p+3 (≡ 2,3 mod 4)
        if (lm == 2) keep = rA;
        else if (lm == 3) keep = rB;

        // one coalesced, lane-permuted 128B warp store per 4 rows
        out[((size_t)k * S_LEN + s0 + 2 * p + lm) * V_DIM + vown] = keep;
    }
}

extern "C" void kernel_launch(void* const* d_in, const int* in_sizes, int n_in,
                              void* d_out, int out_size) {
    // metadata order: block_type_grid (unused), features, mask_idx, head_weights, head_bias
    const float* feats    = (const float*)d_in[1];
    const int*   mask_idx = (const int*)  d_in[2];
    const float* Wh       = (const float*)d_in[3];
    const float* bias     = (const float*)d_in[4];
    float*       out      = (float*)d_out;

    dim3 grid(S_LEN / 256, K_HEADS);   // 64 x 24 blocks, 8 warps each, 32 rows/warp
    attr_decoder_kernel<<<grid, 256>>>(feats, mask_idx, Wh, bias, out);
}

// round 5
// speedup vs baseline: 1.0283x; 1.0283x over previous
#include <cuda_runtime.h>
#include <cstdint>

#define S_LEN 16384
#define D_DIM 256
#define V_DIM 8
#define K_HEADS 24

__device__ __forceinline__ unsigned long long packf2(float lo, float hi) {
    unsigned long long r;
    asm("mov.b64 %0, {%1, %2};" : "=l"(r) : "f"(lo), "f"(hi));
    return r;
}
__device__ __forceinline__ void unpackf2(unsigned long long p, float& lo, float& hi) {
    asm("mov.b64 {%0, %1}, %2;" : "=f"(lo), "=f"(hi) : "l"(p));
}
// d += a*b packed f32x2 (2x fp32 FMA throughput on sm_100+)
__device__ __forceinline__ void fmaf2(unsigned long long& d, unsigned long long a,
                                      unsigned long long b) {
    asm("fma.rn.f32x2 %0, %1, %2, %0;" : "+l"(d) : "l"(a), "l"(b));
}
__device__ __forceinline__ unsigned long long addf2(unsigned long long a,
                                                    unsigned long long b) {
    unsigned long long r;
    asm("add.rn.f32x2 %0, %1, %2;" : "=l"(r) : "l"(a), "l"(b));
    return r;
}
__device__ __forceinline__ unsigned long long shfl_xor64(unsigned long long v, int m) {
    float lo, hi;
    unpackf2(v, lo, hi);
    lo = __shfl_xor_sync(0xffffffffu, lo, m);
    hi = __shfl_xor_sync(0xffffffffu, hi, m);
    return packf2(lo, hi);
}

__global__ __launch_bounds__(256, 2)
void attr_decoder_kernel(const float* __restrict__ feats,      // [N, 256]
                         const int*   __restrict__ mask_idx,   // [24, 16384]
                         const float* __restrict__ Wh,         // [24, 256, 8]
                         const float* __restrict__ bias,       // [24, 8]
                         float*       __restrict__ out)        // [24, 16384, 8]
{
    const int k    = blockIdx.y;
    const int lane = threadIdx.x & 31;
    const int warp = threadIdx.x >> 5;
    const int s0   = blockIdx.x * 256 + warp * 32;   // 32 rows per warp

    const int b4 = (lane >> 4) & 1;
    const int b3 = (lane >> 3) & 1;
    const int b2 = (lane >> 2) & 1;
    const int perm = 2 * b4 + b3;                    // v-pair permutation
    const int vown = 4 * b4 + 2 * b3 + b2;           // v this lane finally owns

    // One gather index per lane covers the warp's 32 rows.
    const int idxv = mask_idx[(size_t)k * S_LEN + s0 + lane];

    // ---- Warm L2 with the ENTIRE 32-row tile this warp will gather.
    // Lane's own idxv is the index of row (s0+lane): 1KB = 8 x 128B lines.
    // Zero registers consumed; converts in-loop DRAM misses into L2 hits.
    {
        const float* myrow = feats + (size_t)idxv * D_DIM;
        #pragma unroll
        for (int j = 0; j < 8; ++j)
            asm volatile("prefetch.global.L2 [%0];" :: "l"(myrow + j * 32));
    }

    // ---- Per-head weights in registers, PRE-PERMUTED so the fold needs no selects.
    // Slot s holds v-pair q = s ^ perm; intra-pair (lo,hi) swapped when b2=1.
    // Lane owns d = lane*8 + i, i in [0,8).
    unsigned long long wp[8][4];
    const float4* wk = (const float4*)(Wh + (size_t)k * (D_DIM * V_DIM));
    #pragma unroll
    for (int i = 0; i < 8; ++i) {
        int d = lane * 8 + i;
        float4 A = wk[d * 2 + 0];
        float4 B = wk[d * 2 + 1];
        float pv[4][2] = {{A.x, A.y}, {A.z, A.w}, {B.x, B.y}, {B.z, B.w}};
        #pragma unroll
        for (int s = 0; s < 4; ++s) {
            int q = s ^ perm;
            wp[i][s] = packf2(pv[q][b2], pv[q][1 - b2]);
        }
    }
    const float bias_v = bias[k * V_DIM + vown];

    // Prefetch row 0 into registers
    int i0 = __shfl_sync(0xffffffffu, idxv, 0);
    const float4* fr0 = (const float4*)(feats + (size_t)i0 * D_DIM) + lane * 2;
    float4 fa = fr0[0];
    float4 fb = fr0[1];

    float keepval = 0.0f;

    #pragma unroll 4
    for (int r = 0; r < 32; ++r) {
        const float4 ca = fa, cb = fb;
        // Register prefetch of next row (now mostly an L2 hit thanks to warm-up)
        if (r + 1 < 32) {
            int ni = __shfl_sync(0xffffffffu, idxv, r + 1);
            const float4* nf = (const float4*)(feats + (size_t)ni * D_DIM) + lane * 2;
            fa = nf[0];
            fb = nf[1];
        }

        // ---- Packed FMA: acc2[s] = partial v-pair (slot s) over this lane's 8 d's.
        const float f[8] = {ca.x, ca.y, ca.z, ca.w, cb.x, cb.y, cb.z, cb.w};
        unsigned long long acc2[4] = {0ull, 0ull, 0ull, 0ull};
        #pragma unroll
        for (int i = 0; i < 8; ++i) {
            unsigned long long fd = packf2(f[i], f[i]);
            #pragma unroll
            for (int s = 0; s < 4; ++s) fmaf2(acc2[s], fd, wp[i][s]);
        }

        // ---- Select-free fold (weights pre-permuted): 9 shfl total.
        // off16: 4 pairs -> 2
        unsigned long long t0 = addf2(acc2[0], shfl_xor64(acc2[2], 16));
        unsigned long long t1 = addf2(acc2[1], shfl_xor64(acc2[3], 16));
        // off8: 2 pairs -> 1 (pair q = perm)
        unsigned long long u2 = addf2(t0, shfl_xor64(t1, 8));
        // off4: intra-pair (pre-swapped by b2)
        float lo, hi;
        unpackf2(u2, lo, hi);
        float w = lo + __shfl_xor_sync(0xffffffffu, hi, 4);
        // remaining lane bits 1,0: plain butterflies
        w += __shfl_xor_sync(0xffffffffu, w, 2);
        w += __shfl_xor_sync(0xffffffffu, w, 1);
        const float res = w + bias_v;   // lane l holds v = vown, replica over l&3

        // Buffer 4 rows (replica (lane&3) keeps row rbase+(lane&3)),
        // then one coalesced, lane-permuted 128B warp store.
        if ((lane & 3) == (r & 3)) keepval = res;
        if ((r & 3) == 3) {
            out[((size_t)k * S_LEN + s0 + (r - 3) + (lane & 3)) * V_DIM + vown] = keepval;
        }
    }
}

extern "C" void kernel_launch(void* const* d_in, const int* in_sizes, int n_in,
                              void* d_out, int out_size) {
    // metadata order: block_type_grid (unused), features, mask_idx, head_weights, head_bias
    const float* feats    = (const float*)d_in[1];
    const int*   mask_idx = (const int*)  d_in[2];
    const float* Wh       = (const float*)d_in[3];
    const float* bias     = (const float*)d_in[4];
    float*       out      = (float*)d_out;

    dim3 grid(S_LEN / 256, K_HEADS);   // 64 x 24 blocks, 8 warps each, 32 rows/warp
    attr_decoder_kernel<<<grid, 256>>>(feats, mask_idx, Wh, bias, out);
}

// round 6
// speedup vs baseline: 1.0991x; 1.0689x over previous
#include <cuda_runtime.h>
#include <cstdint>

#define S_LEN 16384
#define D_DIM 256
#define V_DIM 8
#define K_HEADS 24

__device__ __forceinline__ unsigned long long packf2(float lo, float hi) {
    unsigned long long r;
    asm("mov.b64 %0, {%1, %2};" : "=l"(r) : "f"(lo), "f"(hi));
    return r;
}
__device__ __forceinline__ void unpackf2(unsigned long long p, float& lo, float& hi) {
    asm("mov.b64 {%0, %1}, %2;" : "=f"(lo), "=f"(hi) : "l"(p));
}
// d += a*b packed f32x2 (2x fp32 FMA throughput on sm_100+)
__device__ __forceinline__ void fmaf2(unsigned long long& d, unsigned long long a,
                                      unsigned long long b) {
    asm("fma.rn.f32x2 %0, %1, %2, %0;" : "+l"(d) : "l"(a), "l"(b));
}

__global__ __launch_bounds__(256, 2)
void attr_decoder_kernel(const float* __restrict__ feats,      // [N, 256]
                         const int*   __restrict__ mask_idx,   // [24, 16384]
                         const float* __restrict__ Wh,         // [24, 256, 8]
                         const float* __restrict__ bias,       // [24, 8]
                         float*       __restrict__ out)        // [24, 16384, 8]
{
    const int k    = blockIdx.y;
    const int lane = threadIdx.x & 31;
    const int warp = threadIdx.x >> 5;
    const int s0   = blockIdx.x * 256 + warp * 32;   // 32 rows per warp

    // ---- Per-head weights in registers, packed f32x2 by v-pair.
    // COALESCED lane->d map: lane owns d in {4*lane+j} U {128+4*lane+j}, j=0..3.
    // (feature row then loads as two fully-dense float4 ranges: [0,512) and [512,1024))
    unsigned long long wp[8][4];
    const float4* wk = (const float4*)(Wh + (size_t)k * (D_DIM * V_DIM));
    #pragma unroll
    for (int i = 0; i < 8; ++i) {
        int d = (i < 4) ? (4 * lane + i) : (128 + 4 * lane + (i - 4));
        float4 A = wk[d * 2 + 0];
        float4 B = wk[d * 2 + 1];
        wp[i][0] = packf2(A.x, A.y);
        wp[i][1] = packf2(A.z, A.w);
        wp[i][2] = packf2(B.x, B.y);
        wp[i][3] = packf2(B.z, B.w);
    }
    // After fold-first reduce-scatter, lane l holds v = (l>>2)&7.
    const int  vown   = (lane >> 2) & 7;
    const float bias_v = bias[k * V_DIM + vown];

    // One gather index per lane covers the warp's 32 rows.
    const int idxv = mask_idx[(size_t)k * S_LEN + s0 + lane];

    // Prefetch row 0: lane l reads float4 #lane of each 512B half (dense, coalesced)
    int i0 = __shfl_sync(0xffffffffu, idxv, 0);
    const float4* fr0 = (const float4*)(feats + (size_t)i0 * D_DIM);
    float4 fa = fr0[lane];        // d = 4*lane .. 4*lane+3
    float4 fb = fr0[32 + lane];   // d = 128+4*lane .. 128+4*lane+3

    const bool b4 = (lane & 16) != 0;
    const bool b3 = (lane & 8)  != 0;
    const bool b2 = (lane & 4)  != 0;

    float keepval = 0.0f;

    #pragma unroll 4
    for (int r = 0; r < 32; ++r) {
        const float4 ca = fa, cb = fb;
        // Software prefetch next row (hides L2/DRAM gather latency)
        if (r + 1 < 32) {
            int ni = __shfl_sync(0xffffffffu, idxv, r + 1);
            const float4* nf = (const float4*)(feats + (size_t)ni * D_DIM);
            fa = nf[lane];
            fb = nf[32 + lane];
        }

        // ---- Packed FMA: acc[p] holds partial (v=2p, v=2p+1) over this lane's 8 d's.
        const float f[8] = {ca.x, ca.y, ca.z, ca.w, cb.x, cb.y, cb.z, cb.w};
        unsigned long long acc[4] = {0ull, 0ull, 0ull, 0ull};
        #pragma unroll
        for (int i = 0; i < 8; ++i) {
            unsigned long long fd = packf2(f[i], f[i]);
            #pragma unroll
            for (int p = 0; p < 4; ++p) fmaf2(acc[p], fd, wp[i][p]);
        }
        float a[8];
        #pragma unroll
        for (int p = 0; p < 4; ++p) unpackf2(acc[p], a[2 * p], a[2 * p + 1]);

        // ---- Fold-first reduce-scatter: 9 shfl total (R2 schedule).
        // Stage off16: fold 8 -> 4 (v bit2 chosen by lane bit4)
        float t[4];
        #pragma unroll
        for (int j = 0; j < 4; ++j) {
            float keep = b4 ? a[4 + j] : a[j];
            float send = b4 ? a[j]     : a[4 + j];
            t[j] = keep + __shfl_xor_sync(0xffffffffu, send, 16);
        }
        // Stage off8: fold 4 -> 2 (v bit1 chosen by lane bit3)
        float u[2];
        #pragma unroll
        for (int j = 0; j < 2; ++j) {
            float keep = b3 ? t[2 + j] : t[j];
            float send = b3 ? t[j]     : t[2 + j];
            u[j] = keep + __shfl_xor_sync(0xffffffffu, send, 8);
        }
        // Stage off4: fold 2 -> 1 (v bit0 chosen by lane bit2)
        float keep = b2 ? u[1] : u[0];
        float send = b2 ? u[0] : u[1];
        float w = keep + __shfl_xor_sync(0xffffffffu, send, 4);
        // Remaining sum over lane bits 1,0: plain butterflies
        w += __shfl_xor_sync(0xffffffffu, w, 2);
        w += __shfl_xor_sync(0xffffffffu, w, 1);
        const float res = w + bias_v;   // lane l holds v=(l>>2)&7, replica across l&3

        // Buffer 4 rows (replica (lane&3) keeps row rbase+(lane&3)),
        // then one coalesced, lane-permuted 128B warp store.
        if ((lane & 3) == (r & 3)) keepval = res;
        if ((r & 3) == 3) {
            out[((size_t)k * S_LEN + s0 + (r - 3) + (lane & 3)) * V_DIM + vown] = keepval;
        }
    }
}

extern "C" void kernel_launch(void* const* d_in, const int* in_sizes, int n_in,
                              void* d_out, int out_size) {
    // metadata order: block_type_grid (unused), features, mask_idx, head_weights, head_bias
    const float* feats    = (const float*)d_in[1];
    const int*   mask_idx = (const int*)  d_in[2];
    const float* Wh       = (const float*)d_in[3];
    const float* bias     = (const float*)d_in[4];
    float*       out      = (float*)d_out;

    dim3 grid(S_LEN / 256, K_HEADS);   // 64 x 24 blocks, 8 warps each, 32 rows/warp
    attr_decoder_kernel<<<grid, 256>>>(feats, mask_idx, Wh, bias, out);
}

// round 7
// speedup vs baseline: 1.1021x; 1.0027x over previous
#include <cuda_runtime.h>
#include <cstdint>

#define S_LEN 16384
#define D_DIM 256
#define V_DIM 8
#define K_HEADS 24

typedef unsigned long long u64;

__device__ __forceinline__ u64 packf2(float lo, float hi) {
    u64 r; asm("mov.b64 %0, {%1, %2};" : "=l"(r) : "f"(lo), "f"(hi)); return r;
}
__device__ __forceinline__ void unpackf2(u64 p, float& lo, float& hi) {
    asm("mov.b64 {%0, %1}, %2;" : "=f"(lo), "=f"(hi) : "l"(p));
}
// d += a*b packed f32x2 (2x fp32 FMA throughput on sm_100+)
__device__ __forceinline__ void fmaf2(u64& d, u64 a, u64 b) {
    asm("fma.rn.f32x2 %0, %1, %2, %0;" : "+l"(d) : "l"(a), "l"(b));
}

__global__ __launch_bounds__(256, 3)
void attr_decoder_kernel(const float* __restrict__ feats,      // [N, 256]
                         const int*   __restrict__ mask_idx,   // [24, 16384]
                         const float* __restrict__ Wh,         // [24, 256, 8]
                         const float* __restrict__ bias,       // [24, 8]
                         float*       __restrict__ out)        // [24, 16384, 8]
{
    // Partial sums: [group][d-half][row][v]
    __shared__ float part[4][2][32][V_DIM];

    const int k    = blockIdx.y;
    const int tid  = threadIdx.x;
    const int lane = tid & 31;
    const int warp = tid >> 5;
    const int g    = warp >> 1;      // row group 0..3 (32 rows each)
    const int h    = warp & 1;       // d-half: [128h, 128h+128)
    const int s0   = blockIdx.x * 128 + g * 32;

    // ---- Weights for this lane's 4 d's (d = 128h + 4*lane + j), packed by v-pair.
    u64 wp[4][4];
    const float4* wk = (const float4*)(Wh + (size_t)k * (D_DIM * V_DIM));
    #pragma unroll
    for (int j = 0; j < 4; ++j) {
        int d = h * 128 + 4 * lane + j;
        float4 A = wk[d * 2 + 0];
        float4 B = wk[d * 2 + 1];
        wp[j][0] = packf2(A.x, A.y);
        wp[j][1] = packf2(A.z, A.w);
        wp[j][2] = packf2(B.x, B.y);
        wp[j][3] = packf2(B.z, B.w);
    }
    const int vown = (lane >> 2) & 7;   // after fold, lane l holds v=(l>>2)&7

    // One gather index per lane covers this group's 32 rows.
    const int idxv = mask_idx[(size_t)k * S_LEN + s0 + lane];

    // Half-row load: lane reads float4 #lane of the 512B half (dense, coalesced).
    const float* fbase = feats + h * 128;
    auto loadrow = [&](int r) -> float4 {
        int i = __shfl_sync(0xffffffffu, idxv, r);
        return ((const float4*)(fbase + (size_t)i * D_DIM))[lane];
    };

    // Depth-3 register prefetch pipeline.
    float4 buf0 = loadrow(0);
    float4 buf1 = loadrow(1);
    float4 buf2 = loadrow(2);

    const bool b4 = (lane & 16) != 0;
    const bool b3 = (lane & 8)  != 0;
    const bool b2 = (lane & 4)  != 0;
    float keepval = 0.0f;

    #pragma unroll
    for (int r = 0; r < 32; ++r) {
        const float4 cur = (r % 3 == 0) ? buf0 : ((r % 3 == 1) ? buf1 : buf2);
        if (r + 3 < 32) {
            float4 nx = loadrow(r + 3);
            if (r % 3 == 0) buf0 = nx;
            else if (r % 3 == 1) buf1 = nx;
            else buf2 = nx;
        }

        // ---- Packed FMA over this lane's 4 d's: acc[p] = partial (v=2p, v=2p+1).
        const float f[4] = {cur.x, cur.y, cur.z, cur.w};
        u64 acc[4] = {0ull, 0ull, 0ull, 0ull};
        #pragma unroll
        for (int j = 0; j < 4; ++j) {
            u64 fd = packf2(f[j], f[j]);
            #pragma unroll
            for (int p = 0; p < 4; ++p) fmaf2(acc[p], fd, wp[j][p]);
        }
        float a[8];
        #pragma unroll
        for (int p = 0; p < 4; ++p) unpackf2(acc[p], a[2 * p], a[2 * p + 1]);

        // ---- Fold-first reduce-scatter (9 shfl): lane l ends with v=(l>>2)&7
        // summed over all 128 d's of this half.
        float t[4];
        #pragma unroll
        for (int j = 0; j < 4; ++j) {
            float keep = b4 ? a[4 + j] : a[j];
            float send = b4 ? a[j]     : a[4 + j];
            t[j] = keep + __shfl_xor_sync(0xffffffffu, send, 16);
        }
        float u[2];
        #pragma unroll
        for (int j = 0; j < 2; ++j) {
            float keep = b3 ? t[2 + j] : t[j];
            float send = b3 ? t[j]     : t[2 + j];
            u[j] = keep + __shfl_xor_sync(0xffffffffu, send, 8);
        }
        float keep = b2 ? u[1] : u[0];
        float send = b2 ? u[0] : u[1];
        float w = keep + __shfl_xor_sync(0xffffffffu, send, 4);
        w += __shfl_xor_sync(0xffffffffu, w, 2);
        w += __shfl_xor_sync(0xffffffffu, w, 1);
        // w is replicated across (lane&3); NO bias here (added in epilogue).

        // Buffer 4 rows, then one conflict-free 128B smem store
        // (lane = 4*vown + m stores row rbase+m, v=vown -> 32 distinct banks).
        if ((lane & 3) == (r & 3)) keepval = w;
        if ((r & 3) == 3) {
            part[g][h][(r - 3) + (lane & 3)][vown] = keepval;
        }
    }

    __syncthreads();

    // ---- Epilogue: combine d-halves + bias; fully-coalesced float4 stores.
    // CTA covers 128 rows x 8 v = 1024 floats = 256 threads x float4.
    {
        const int row = tid >> 1;            // 0..127
        const int gg  = row >> 5;
        const int rl  = row & 31;
        const int v0  = (tid & 1) * 4;
        const float4 p0 = *(const float4*)&part[gg][0][rl][v0];
        const float4 p1 = *(const float4*)&part[gg][1][rl][v0];
        const float4 bv = *(const float4*)(bias + k * V_DIM + v0);
        float4 o;
        o.x = p0.x + p1.x + bv.x;
        o.y = p0.y + p1.y + bv.y;
        o.z = p0.z + p1.z + bv.z;
        o.w = p0.w + p1.w + bv.w;
        float4* ob = (float4*)out + ((size_t)k * S_LEN + blockIdx.x * 128) * 2;
        ob[tid] = o;
    }
}

extern "C" void kernel_launch(void* const* d_in, const int* in_sizes, int n_in,
                              void* d_out, int out_size) {
    // metadata order: block_type_grid (unused), features, mask_idx, head_weights, head_bias
    const float* feats    = (const float*)d_in[1];
    const int*   mask_idx = (const int*)  d_in[2];
    const float* Wh       = (const float*)d_in[3];
    const float* bias     = (const float*)d_in[4];
    float*       out      = (float*)d_out;

    dim3 grid(S_LEN / 128, K_HEADS);   // 128 x 24 CTAs; warp pair per 32-row group
    attr_decoder_kernel<<<grid, 256>>>(feats, mask_idx, Wh, bias, out);
}